// round 2
// baseline (speedup 1.0000x reference)
#include <cuda_runtime.h>
#include <math.h>

#define TOKENS 8192
#define DIM    1024
#define NQKV   3072
#define HEADS  16
#define DH     64
#define SEG    512
#define NPM    16

// ---------------- scratch (allocation-free: __device__ globals) ----------------
__device__ float g_xn [(size_t)TOKENS * DIM];    // normalized input
__device__ float g_qkv[(size_t)TOKENS * NQKV];   // qkv projection (token-major)
__device__ float g_q  [(size_t)TOKENS * DIM];    // q, roped, (bw,h,s,d)
__device__ float g_k  [(size_t)TOKENS * DIM];    // k, roped, (bw,h,s,d)
__device__ float g_ao [(size_t)TOKENS * DIM];    // attention out (token-major)
__device__ float g_cos[SEG * 32];
__device__ float g_sin[SEG * 32];

// ---------------- rope table (double precision to match fp32 reference) -------
__global__ void rope_table_kernel() {
    int idx = blockIdx.x * blockDim.x + threadIdx.x;
    if (idx >= SEG * 32) return;
    int s = idx >> 5, i = idx & 31;
    double invf = pow(10000.0, -(double)(2 * i) / 64.0);
    double ang = (double)s * invf;
    g_cos[idx] = (float)cos(ang);
    g_sin[idx] = (float)sin(ang);
}

// ---------------- RMSNorm -----------------------------------------------------
__global__ __launch_bounds__(256) void rmsnorm_kernel(const float* __restrict__ seq,
                                                      const float* __restrict__ w) {
    int t = blockIdx.x;
    const float* x = seq + (size_t)t * DIM;
    float* y = g_xn + (size_t)t * DIM;
    float ss = 0.f;
    for (int i = threadIdx.x; i < DIM; i += 256) { float v = x[i]; ss += v * v; }
    __shared__ float red[8];
    #pragma unroll
    for (int o = 16; o > 0; o >>= 1) ss += __shfl_xor_sync(0xffffffffu, ss, o);
    if ((threadIdx.x & 31) == 0) red[threadIdx.x >> 5] = ss;
    __syncthreads();
    if (threadIdx.x < 8) {
        float v = red[threadIdx.x];
        #pragma unroll
        for (int o = 4; o > 0; o >>= 1) v += __shfl_xor_sync(0xffu, v, o);
        if (threadIdx.x == 0) red[0] = v;
    }
    __syncthreads();
    float r = rsqrtf(red[0] * (1.0f / DIM) + 1.1920929e-07f);
    for (int i = threadIdx.x; i < DIM; i += 256) y[i] = x[i] * r * w[i];
}

// ---------------- tiled fp32 GEMM: C[M,N] = A[M,K] @ B[K,N] -------------------
// MODE 0: A = g_xn, C = g_qkv.   MODE 1: A = g_ao, C = Cout (d_out).
template <int MODE>
__global__ __launch_bounds__(256) void sgemm_kernel(const float* __restrict__ B,
                                                    float* __restrict__ Cout,
                                                    int M, int N, int K) {
    constexpr int BM = 128, BN = 128, BK = 8, TM = 8, TN = 8;
    const float* A = (MODE == 0) ? g_xn : g_ao;
    float* C = (MODE == 0) ? g_qkv : Cout;

    __shared__ __align__(16) float As[BK * BM];
    __shared__ __align__(16) float Bs[BK * BN];

    int tid = threadIdx.x;
    int rowBase = blockIdx.y * BM;
    int colBase = blockIdx.x * BN;

    int aRow  = tid >> 1;           // 0..127
    int aCol4 = (tid & 1) * 4;      // 0 or 4
    int bRow  = tid >> 5;           // 0..7
    int bCol4 = (tid & 31) * 4;     // 0..124
    int tr = (tid / 16) * TM;
    int tc = (tid % 16) * TN;

    float acc[TM * TN];
    #pragma unroll
    for (int i = 0; i < TM * TN; i++) acc[i] = 0.f;

    const float* Aptr = A + (size_t)rowBase * K;
    const float* Bptr = B + colBase;

    for (int k0 = 0; k0 < K; k0 += BK) {
        float4 a = *(const float4*)(Aptr + (size_t)aRow * K + k0 + aCol4);
        As[(aCol4 + 0) * BM + aRow] = a.x;
        As[(aCol4 + 1) * BM + aRow] = a.y;
        As[(aCol4 + 2) * BM + aRow] = a.z;
        As[(aCol4 + 3) * BM + aRow] = a.w;
        *(float4*)(Bs + bRow * BN + bCol4) =
            *(const float4*)(Bptr + (size_t)(k0 + bRow) * N + bCol4);
        __syncthreads();
        #pragma unroll
        for (int k = 0; k < BK; k++) {
            float rm[TM], rn[TN];
            #pragma unroll
            for (int m = 0; m < TM; m += 4) *(float4*)(rm + m) = *(const float4*)(As + k * BM + tr + m);
            #pragma unroll
            for (int n = 0; n < TN; n += 4) *(float4*)(rn + n) = *(const float4*)(Bs + k * BN + tc + n);
            #pragma unroll
            for (int m = 0; m < TM; m++)
                #pragma unroll
                for (int n = 0; n < TN; n++)
                    acc[m * TN + n] = fmaf(rm[m], rn[n], acc[m * TN + n]);
        }
        __syncthreads();
    }
    #pragma unroll
    for (int m = 0; m < TM; m++) {
        size_t r = rowBase + tr + m;
        #pragma unroll
        for (int n = 0; n < TN; n += 4)
            *(float4*)(C + r * N + colBase + tc + n) =
                make_float4(acc[m * TN + n], acc[m * TN + n + 1],
                            acc[m * TN + n + 2], acc[m * TN + n + 3]);
    }
}

// ---------------- scatter qkv to (bw,h,s,d) + RoPE on q,k; v -> d_out ---------
__global__ __launch_bounds__(256) void scatter_rope_kernel(float* __restrict__ out_v) {
    int p = blockIdx.x * blockDim.x + threadIdx.x;     // pair index
    if (p >= TOKENS * (NQKV / 2)) return;
    int t = p / (NQKV / 2);
    int n = (p % (NQKV / 2)) * 2;
    float x0 = g_qkv[(size_t)t * NQKV + n];
    float x1 = g_qkv[(size_t)t * NQKV + n + 1];
    int bw = t / SEG, s = t % SEG;
    int which = n >> 10;          // 0=q, 1=k, 2=v
    int nn = n & 1023;
    int h = nn >> 6, d = nn & 63;
    size_t dst = ((size_t)(bw * HEADS + h) * SEG + s) * DH + d;
    if (which == 2) { out_v[dst] = x0; out_v[dst + 1] = x1; return; }
    float c  = g_cos[s * 32 + (d >> 1)];
    float sn = g_sin[s * 32 + (d >> 1)];
    float y0 = x0 * c - x1 * sn;
    float y1 = x1 * c + x0 * sn;
    float* dstp = which ? g_k : g_q;
    dstp[dst] = y0; dstp[dst + 1] = y1;
}

// ---------------- flash attention: 1 thread = 1 query row ---------------------
// grid (256 head-instances, 4 q-tiles of 128), block 128
__global__ __launch_bounds__(128) void attn_kernel(const float* __restrict__ vsrc,
                                                   const float* __restrict__ pmem) {
    int bwh = blockIdx.x;
    int h = bwh % HEADS;
    int qt = blockIdx.y;
    int tid = threadIdx.x;

    __shared__ __align__(16) float sm[128 * 64];   // 32 KB, reused Q -> (K,V)

    const float* Qb = g_q + ((size_t)bwh * SEG + qt * 128) * DH;
    for (int e = tid; e < 128 * 64; e += 128) sm[e] = Qb[e];
    __syncthreads();
    float q[DH];
    #pragma unroll
    for (int d4 = 0; d4 < DH / 4; d4++) {
        float4 v = *(const float4*)(sm + tid * DH + d4 * 4);
        q[d4 * 4 + 0] = v.x * 0.125f; q[d4 * 4 + 1] = v.y * 0.125f;
        q[d4 * 4 + 2] = v.z * 0.125f; q[d4 * 4 + 3] = v.w * 0.125f;
    }
    __syncthreads();

    float acc[DH];
    #pragma unroll
    for (int d = 0; d < DH; d++) acc[d] = 0.f;
    float m = -1e30f, l = 0.f;
    int i = qt * 128 + tid;
    int nkeys = NPM + i + 1;                            // visible keys for this row
    int nch = (NPM + (qt + 1) * 128 + 63) / 64;         // chunks needed by this tile

    const float* Kb = g_k + (size_t)bwh * SEG * DH;
    const float* Vb = vsrc + (size_t)bwh * SEG * DH;
    const float* PK = pmem + (size_t)h * NPM * DH;
    const float* PV = pmem + (size_t)HEADS * NPM * DH + (size_t)h * NPM * DH;
    float* Ks = sm;
    float* Vs = sm + 64 * 64;

    for (int c = 0; c < nch; c++) {
        for (int e = tid; e < 64 * 64; e += 128) {
            int j = c * 64 + (e >> 6); int d = e & 63;
            float kv, vv;
            if (j < NPM)            { kv = PK[j * DH + d];                   vv = PV[j * DH + d]; }
            else if (j < NPM + SEG) { kv = Kb[(size_t)(j - NPM) * DH + d];   vv = Vb[(size_t)(j - NPM) * DH + d]; }
            else                    { kv = 0.f; vv = 0.f; }
            Ks[e] = kv; Vs[e] = vv;
        }
        __syncthreads();
        int jvalid = nkeys - c * 64;   // keys j < jvalid are visible in this chunk
        #pragma unroll 2
        for (int j = 0; j < 64; j++) {
            float s = 0.f;
            const float4* kp = (const float4*)(Ks + j * 64);
            #pragma unroll
            for (int d4 = 0; d4 < DH / 4; d4++) {
                float4 kk = kp[d4];
                s = fmaf(q[d4 * 4 + 0], kk.x, s);
                s = fmaf(q[d4 * 4 + 1], kk.y, s);
                s = fmaf(q[d4 * 4 + 2], kk.z, s);
                s = fmaf(q[d4 * 4 + 3], kk.w, s);
            }
            if (j >= jvalid) s = -1e30f;     // causal mask + beyond-row padding
            if (s > m) {
                float corr = __expf(m - s);
                l *= corr;
                #pragma unroll
                for (int d = 0; d < DH; d++) acc[d] *= corr;
                m = s;
            }
            float p = __expf(s - m);
            l += p;
            const float4* vp = (const float4*)(Vs + j * 64);
            #pragma unroll
            for (int d4 = 0; d4 < DH / 4; d4++) {
                float4 vv = vp[d4];
                acc[d4 * 4 + 0] = fmaf(p, vv.x, acc[d4 * 4 + 0]);
                acc[d4 * 4 + 1] = fmaf(p, vv.y, acc[d4 * 4 + 1]);
                acc[d4 * 4 + 2] = fmaf(p, vv.z, acc[d4 * 4 + 2]);
                acc[d4 * 4 + 3] = fmaf(p, vv.w, acc[d4 * 4 + 3]);
            }
        }
        __syncthreads();
    }
    int bw = bwh / HEADS;
    float rl = 1.0f / l;
    float* outp = g_ao + ((size_t)(bw * SEG + i)) * DIM + (size_t)h * DH;
    #pragma unroll
    for (int d = 0; d < DH; d += 4)
        *(float4*)(outp + d) = make_float4(acc[d] * rl, acc[d + 1] * rl,
                                           acc[d + 2] * rl, acc[d + 3] * rl);
}

// ---------------- launch ------------------------------------------------------
extern "C" void kernel_launch(void* const* d_in, const int* in_sizes, int n_in,
                              void* d_out, int out_size) {
    const float* seq    = (const float*)d_in[0];
    const float* norm_w = (const float*)d_in[1];
    const float* w_qkv  = (const float*)d_in[2];
    const float* w_out  = (const float*)d_in[3];
    const float* pmem   = (const float*)d_in[4];
    float* out   = (float*)d_out;
    float* out_v = out + (size_t)TOKENS * DIM;   // second output: orig_v

    rope_table_kernel<<<64, 256>>>();
    rmsnorm_kernel<<<TOKENS, 256>>>(seq, norm_w);
    sgemm_kernel<0><<<dim3(NQKV / 128, TOKENS / 128), 256>>>(w_qkv, nullptr, TOKENS, NQKV, DIM);
    scatter_rope_kernel<<<(TOKENS * (NQKV / 2) + 255) / 256, 256>>>(out_v);
    attn_kernel<<<dim3(256, 4), 128>>>(out_v, pmem);
    sgemm_kernel<1><<<dim3(DIM / 128, TOKENS / 128), 256>>>(w_out, out, TOKENS, DIM, DIM);
}

// round 11
// speedup vs baseline: 1.0584x; 1.0584x over previous
#include <cuda_runtime.h>
#include <cuda_bf16.h>
#include <math.h>
#include <stdint.h>

#define TOKENS 8192
#define DIM    1024
#define NQKV   3072
#define HEADS  16
#define DH     64
#define SEG    512
#define NPM    16

// ---------------- scratch (allocation-free: __device__ globals) ----------------
__device__ __align__(16) float g_xn [(size_t)TOKENS * DIM];    // normalized input
__device__ __align__(16) float g_qkv[(size_t)TOKENS * NQKV];   // qkv projection
__device__ __align__(16) float g_q  [(size_t)TOKENS * DIM];    // q roped (bw,h,s,d)
__device__ __align__(16) float g_k  [(size_t)TOKENS * DIM];    // k roped (bw,h,s,d)
__device__ __align__(16) float g_ao [(size_t)TOKENS * DIM];    // attention out
__device__ float g_cos[SEG * 32];
__device__ float g_sin[SEG * 32];

// ---------------- rope table (double precision) -------------------------------
__global__ void rope_table_kernel() {
    int idx = blockIdx.x * blockDim.x + threadIdx.x;
    if (idx >= SEG * 32) return;
    int s = idx >> 5, i = idx & 31;
    double invf = pow(10000.0, -(double)(2 * i) / 64.0);
    double ang = (double)s * invf;
    g_cos[idx] = (float)cos(ang);
    g_sin[idx] = (float)sin(ang);
}

// ---------------- RMSNorm -----------------------------------------------------
__global__ __launch_bounds__(256) void rmsnorm_kernel(const float* __restrict__ seq,
                                                      const float* __restrict__ w) {
    int t = blockIdx.x;
    const float* x = seq + (size_t)t * DIM;
    float* y = g_xn + (size_t)t * DIM;
    float ss = 0.f;
    for (int i = threadIdx.x; i < DIM; i += 256) { float v = x[i]; ss += v * v; }
    __shared__ float red[8];
    #pragma unroll
    for (int o = 16; o > 0; o >>= 1) ss += __shfl_xor_sync(0xffffffffu, ss, o);
    if ((threadIdx.x & 31) == 0) red[threadIdx.x >> 5] = ss;
    __syncthreads();
    if (threadIdx.x < 8) {
        float v = red[threadIdx.x];
        #pragma unroll
        for (int o = 4; o > 0; o >>= 1) v += __shfl_xor_sync(0xffu, v, o);
        if (threadIdx.x == 0) red[0] = v;
    }
    __syncthreads();
    float r = rsqrtf(red[0] * (1.0f / DIM) + 1.1920929e-07f);
    for (int i = threadIdx.x; i < DIM; i += 256) y[i] = x[i] * r * w[i];
}

// ---------------- tiled fp32 GEMM, BK=16 + register prefetch -------------------
// C[M,N] = A[M,1024] @ B[1024,N].  MODE 0: A=g_xn, C=g_qkv.  MODE 1: A=g_ao, C=Cout.
template <int MODE>
__global__ __launch_bounds__(256) void sgemm_kernel(const float* __restrict__ B,
                                                    float* __restrict__ Cout, int N) {
    constexpr int BM = 128, BN = 128, BK = 16, TM = 8, TN = 8;
    const float* A = (MODE == 0) ? g_xn : g_ao;
    float* C = (MODE == 0) ? g_qkv : Cout;

    __shared__ __align__(16) float As[BK][BM];
    __shared__ __align__(16) float Bs[BK][BN];

    int tid = threadIdx.x;
    int rowBase = blockIdx.y * BM;
    int colBase = blockIdx.x * BN;

    int lrow = tid >> 1, lk = (tid & 1) * 8;      // A: 128 rows x 16 k, 8 elems/thread
    int brow = tid >> 4, bc = (tid & 15) * 8;     // B: 16 rows x 128 cols, 8 elems/thread
    int tr = (tid / 16) * TM;
    int tc = (tid % 16) * TN;

    const float* Ap = A + (size_t)rowBase * DIM + (size_t)lrow * DIM + lk;
    const float* Bp = B + colBase + (size_t)brow * N + bc;

    float acc[TM * TN];
    #pragma unroll
    for (int i = 0; i < TM * TN; i++) acc[i] = 0.f;

    // prefetch stage 0 into registers
    float4 pa0 = *(const float4*)(Ap + 0);
    float4 pa1 = *(const float4*)(Ap + 4);
    float4 pb0 = *(const float4*)(Bp + 0);
    float4 pb1 = *(const float4*)(Bp + 4);

    const int KT = DIM / BK;                       // 64 stages
    for (int kt = 0; kt < KT; kt++) {
        // store current stage (A transposed to [k][m])
        As[lk + 0][lrow] = pa0.x; As[lk + 1][lrow] = pa0.y;
        As[lk + 2][lrow] = pa0.z; As[lk + 3][lrow] = pa0.w;
        As[lk + 4][lrow] = pa1.x; As[lk + 5][lrow] = pa1.y;
        As[lk + 6][lrow] = pa1.z; As[lk + 7][lrow] = pa1.w;
        *(float4*)(&Bs[brow][bc])     = pb0;
        *(float4*)(&Bs[brow][bc + 4]) = pb1;
        __syncthreads();

        if (kt + 1 < KT) {                          // overlap next-stage loads with compute
            const float* an = Ap + (kt + 1) * BK;
            const float* bn = Bp + (size_t)(kt + 1) * BK * N;
            pa0 = *(const float4*)(an + 0);
            pa1 = *(const float4*)(an + 4);
            pb0 = *(const float4*)(bn + 0);
            pb1 = *(const float4*)(bn + 4);
        }

        #pragma unroll
        for (int k = 0; k < BK; k++) {
            float rm[TM], rn[TN];
            #pragma unroll
            for (int m = 0; m < TM; m += 4) *(float4*)(rm + m) = *(const float4*)(&As[k][tr + m]);
            #pragma unroll
            for (int n = 0; n < TN; n += 4) *(float4*)(rn + n) = *(const float4*)(&Bs[k][tc + n]);
            #pragma unroll
            for (int m = 0; m < TM; m++)
                #pragma unroll
                for (int n = 0; n < TN; n++)
                    acc[m * TN + n] = fmaf(rm[m], rn[n], acc[m * TN + n]);
        }
        __syncthreads();
    }

    #pragma unroll
    for (int m = 0; m < TM; m++) {
        size_t r = rowBase + tr + m;
        #pragma unroll
        for (int n = 0; n < TN; n += 4)
            *(float4*)(C + r * N + colBase + tc + n) =
                make_float4(acc[m * TN + n], acc[m * TN + n + 1],
                            acc[m * TN + n + 2], acc[m * TN + n + 3]);
    }
}

// ---------------- scatter qkv to (bw,h,s,d) + RoPE; v -> d_out ----------------
__global__ __launch_bounds__(256) void scatter_rope_kernel(float* __restrict__ out_v) {
    int p = blockIdx.x * blockDim.x + threadIdx.x;
    if (p >= TOKENS * (NQKV / 2)) return;
    int t = p / (NQKV / 2);
    int n = (p % (NQKV / 2)) * 2;
    float x0 = g_qkv[(size_t)t * NQKV + n];
    float x1 = g_qkv[(size_t)t * NQKV + n + 1];
    int bw = t / SEG, s = t % SEG;
    int which = n >> 10;          // 0=q, 1=k, 2=v
    int nn = n & 1023;
    int h = nn >> 6, d = nn & 63;
    size_t dst = ((size_t)(bw * HEADS + h) * SEG + s) * DH + d;
    if (which == 2) { out_v[dst] = x0; out_v[dst + 1] = x1; return; }
    float c  = g_cos[s * 32 + (d >> 1)];
    float sn = g_sin[s * 32 + (d >> 1)];
    float y0 = x0 * c - x1 * sn;
    float y1 = x1 * c + x0 * sn;
    float* dstp = which ? g_k : g_q;
    dstp[dst] = y0; dstp[dst + 1] = y1;
}

// ---------------- flash attention: 1 thread = 1 query row ---------------------
__global__ __launch_bounds__(128) void attn_kernel(const float* __restrict__ vsrc,
                                                   const float* __restrict__ pmem) {
    int bwh = blockIdx.x;
    int h = bwh % HEADS;
    int qt = blockIdx.y;
    int tid = threadIdx.x;

    __shared__ __align__(16) float sm[128 * 64];

    const float* Qb = g_q + ((size_t)bwh * SEG + qt * 128) * DH;
    for (int e = tid; e < 128 * 64; e += 128) sm[e] = Qb[e];
    __syncthreads();
    float q[DH];
    #pragma unroll
    for (int d4 = 0; d4 < DH / 4; d4++) {
        float4 v = *(const float4*)(sm + tid * DH + d4 * 4);
        q[d4 * 4 + 0] = v.x * 0.125f; q[d4 * 4 + 1] = v.y * 0.125f;
        q[d4 * 4 + 2] = v.z * 0.125f; q[d4 * 4 + 3] = v.w * 0.125f;
    }
    __syncthreads();

    float acc[DH];
    #pragma unroll
    for (int d = 0; d < DH; d++) acc[d] = 0.f;
    float m = -1e30f, l = 0.f;
    int i = qt * 128 + tid;
    int nkeys = NPM + i + 1;
    int nch = (NPM + (qt + 1) * 128 + 63) / 64;

    const float* Kb = g_k + (size_t)bwh * SEG * DH;
    const float* Vb = vsrc + (size_t)bwh * SEG * DH;
    const float* PK = pmem + (size_t)h * NPM * DH;
    const float* PV = pmem + (size_t)HEADS * NPM * DH + (size_t)h * NPM * DH;
    float* Ks = sm;
    float* Vs = sm + 64 * 64;

    for (int c = 0; c < nch; c++) {
        for (int e = tid; e < 64 * 64; e += 128) {
            int j = c * 64 + (e >> 6); int d = e & 63;
            float kv, vv;
            if (j < NPM)            { kv = PK[j * DH + d];                 vv = PV[j * DH + d]; }
            else if (j < NPM + SEG) { kv = Kb[(size_t)(j - NPM) * DH + d]; vv = Vb[(size_t)(j - NPM) * DH + d]; }
            else                    { kv = 0.f; vv = 0.f; }
            Ks[e] = kv; Vs[e] = vv;
        }
        __syncthreads();
        int jvalid = nkeys - c * 64;
        #pragma unroll 2
        for (int j = 0; j < 64; j++) {
            float s = 0.f;
            const float4* kp = (const float4*)(Ks + j * 64);
            #pragma unroll
            for (int d4 = 0; d4 < DH / 4; d4++) {
                float4 kk = kp[d4];
                s = fmaf(q[d4 * 4 + 0], kk.x, s);
                s = fmaf(q[d4 * 4 + 1], kk.y, s);
                s = fmaf(q[d4 * 4 + 2], kk.z, s);
                s = fmaf(q[d4 * 4 + 3], kk.w, s);
            }
            if (j >= jvalid) s = -1e30f;
            if (s > m) {
                float corr = __expf(m - s);
                l *= corr;
                #pragma unroll
                for (int d = 0; d < DH; d++) acc[d] *= corr;
                m = s;
            }
            float p = __expf(s - m);
            l += p;
            const float4* vp = (const float4*)(Vs + j * 64);
            #pragma unroll
            for (int d4 = 0; d4 < DH / 4; d4++) {
                float4 vv = vp[d4];
                acc[d4 * 4 + 0] = fmaf(p, vv.x, acc[d4 * 4 + 0]);
                acc[d4 * 4 + 1] = fmaf(p, vv.y, acc[d4 * 4 + 1]);
                acc[d4 * 4 + 2] = fmaf(p, vv.z, acc[d4 * 4 + 2]);
                acc[d4 * 4 + 3] = fmaf(p, vv.w, acc[d4 * 4 + 3]);
            }
        }
        __syncthreads();
    }
    int bw = bwh / HEADS;
    float rl = 1.0f / l;
    float* outp = g_ao + ((size_t)(bw * SEG + i)) * DIM + (size_t)h * DH;
    #pragma unroll
    for (int d = 0; d < DH; d += 4)
        *(float4*)(outp + d) = make_float4(acc[d] * rl, acc[d + 1] * rl,
                                           acc[d + 2] * rl, acc[d + 3] * rl);
}

// ---------------- launch ------------------------------------------------------
extern "C" void kernel_launch(void* const* d_in, const int* in_sizes, int n_in,
                              void* d_out, int out_size) {
    const float* seq    = (const float*)d_in[0];
    const float* norm_w = (const float*)d_in[1];
    const float* w_qkv  = (const float*)d_in[2];
    const float* w_out  = (const float*)d_in[3];
    const float* pmem   = (const float*)d_in[4];
    float* out   = (float*)d_out;
    float* out_v = out + (size_t)TOKENS * DIM;   // second output: orig_v

    rope_table_kernel<<<64, 256>>>();
    rmsnorm_kernel<<<TOKENS, 256>>>(seq, norm_w);
    sgemm_kernel<0><<<dim3(NQKV / 128, TOKENS / 128), 256>>>(w_qkv, nullptr, NQKV);
    scatter_rope_kernel<<<(TOKENS * (NQKV / 2) + 255) / 256, 256>>>(out_v);
    attn_kernel<<<dim3(256, 4), 128>>>(out_v, pmem);
    sgemm_kernel<1><<<dim3(DIM / 128, TOKENS / 128), 256>>>(w_out, out, DIM);
}